// round 12
// baseline (speedup 1.0000x reference)
#include <cuda_runtime.h>
#include <stdint.h>

namespace {

constexpr int WPB = 4;                  // warps (= images) per block
constexpr int THREADS = WPB * 32;

// Scale chain in double exactly like Python floats, cast to f32 at use.
constexpr double S0d = 0.05;
constexpr double C1d = S0d * 0.05;
constexpr double S1d = C1d * 16.0;
constexpr double C2d = S1d * 0.05;
constexpr double S2d = C2d * 16.0;
constexpr double C3d = S2d * 0.05;
constexpr double S3d = C3d * 16.0;
constexpr double C4d = S3d * 0.05;

// XLA rewrites x/const -> x * fl32(1/const)
constexpr float I0F = 1.0f / (float)S0d;
constexpr float C1F = (float)C1d;  constexpr float I1F = 1.0f / (float)S1d;
constexpr float C2F = (float)C2d;  constexpr float I2F = 1.0f / (float)S2d;
constexpr float C3F = (float)C3d;  constexpr float I3F = 1.0f / (float)S3d;
constexpr float C4F = (float)C4d;

__device__ __forceinline__ int f2i(float f) { return __float2int_rn(f); }

__device__ __forceinline__ int pk(int a, int b, int c, int d) {
    return (a & 255) | ((b & 255) << 8) | ((c & 255) << 16) | ((d & 255) << 24);
}

// Layer-1 quantize: bounds proven (0 <= m <= 1440 -> 0 <= q <= 90), no clamp.
// __fmul_rn forbids FMA contraction; two multiplies must match XLA exactly.
__device__ __forceinline__ int qnc(int m, float C, float I) {
    return __float2int_rn(__fmul_rn(__fmul_rn(__int2float_rn(m), C), I));
}
// Clamped quantize (m >= 0 post-relu, so only the upper clip can bind).
__device__ __forceinline__ int qcl(int m, float C, float I) {
    float z = __fmul_rn(__fmul_rn(__int2float_rn(m), C), I);
    return __float2int_rn(fminf(z, 127.0f));
}

// (a.b0, b.b0, c.b0, d.b0) -> one word. Selector nibbles LSB-first.
__device__ __forceinline__ uint32_t pack4(int a, int b, int c, int d) {
    return __byte_perm(__byte_perm(a, b, 0x0040), __byte_perm(c, d, 0x0040), 0x5410);
}

__device__ __forceinline__ int dp3(uint32_t r0, uint32_t r1, uint32_t r2,
                                   int k0, int k1, int k2) {
    return __dp4a((int)r0, k0, __dp4a((int)r1, k1, __dp4a((int)r2, k2, 0)));
}

struct __align__(16) WS {
    uint32_t qin[198];       // 28 rows x 7 words, contiguous (+2 pad: OOB guard + align)
    uint32_t q2[13 * 14];    // 13 rows, stride 14 words (even => 8B-aligned uint2 reads)
    uint32_t q3[26];         // 5x5 cells, 4 ch packed per word (+pad)
};

__global__ void __launch_bounds__(THREADS, 14) qcnn_kernel(
    const float* __restrict__ x,
    const float* __restrict__ w1,
    const float* __restrict__ w2,
    const float* __restrict__ w3,
    const float* __restrict__ w4,
    float* __restrict__ out,
    int B)
{
    __shared__ WS ws[WPB];
    __shared__ int wp1[4][3];   // [oc][ky]: (w[ky,0],w[ky,1],w[ky,2],0)
    __shared__ int wp2[4][9];   // [oc][ky*3+kx]: 4 in-ch packed
    __shared__ int wp3[4][9];
    __shared__ int wp4[12];

    const int tid = threadIdx.x;

    // ---- pack integer weights into dp4a operands (once per block) ----
    if (tid < 12) {
        int oc = tid / 3, ky = tid % 3;
        const float* p = w1 + (ky * 3) * 16 + oc;     // HWIO, ic=0, kx stride 16
        wp1[oc][ky] = pk(f2i(p[0]), f2i(p[16]), f2i(p[32]), 0);
    } else if (tid < 48) {
        int j = tid - 12, oc = j / 9, k = j % 9;
        const float* p = w2 + k * 16 + oc;
        wp2[oc][k] = pk(f2i(p[0]), f2i(p[4]), f2i(p[8]), f2i(p[12]));
    } else if (tid < 84) {
        int j = tid - 48, oc = j / 9, k = j % 9;
        const float* p = w3 + k * 16 + oc;
        wp3[oc][k] = pk(f2i(p[0]), f2i(p[4]), f2i(p[8]), f2i(p[12]));
    } else if (tid < 96) {
        int oc = tid - 84;
        wp4[oc] = pk(f2i(w4[oc]), f2i(w4[12 + oc]), f2i(w4[24 + oc]), f2i(w4[36 + oc]));
    }
    __syncthreads();

    const int lane = tid & 31;
    const int wrp  = tid >> 5;
    const int img  = blockIdx.x * WPB + wrp;
    if (img >= B) return;
    WS& s = ws[wrp];

    // ---- stage 0: quantize input; pack 4 px/word (contiguous, no row pad) ----
    {
        const float4* xi4 = (const float4*)(x + (size_t)img * 784);
        for (int g = lane; g < 196; g += 32) {
            float4 v = xi4[g];
            int a = __float2int_rn(__fmul_rn(v.x, I0F));
            int b = __float2int_rn(__fmul_rn(v.y, I0F));
            int c = __float2int_rn(__fmul_rn(v.z, I0F));
            int d = __float2int_rn(__fmul_rn(v.w, I0F));
            s.qin[g] = pack4(a, b, c, d);
        }
    }
    __syncwarp();

    // ---- stage 1: conv1(3x3,1->4) + maxpool2x2 + relu + quant -> q2[13][13] ----
    // Fused px-pair tasks: task u = (py, pp) computes pooled outputs px0=2pp, px0+1.
    // 13 rows x 7 pairs = 91 tasks -> 3 warp iterations.
    {
        #pragma unroll
        for (int it = 0; it < 3; it++) {
            int u = lane + it * 32;
            if (u < 91) {
                int py = u / 7, pp = u - py * 7;
                int base = py * 14 + pp;                 // word of byte 4*pp in row 2*py
                uint32_t P0[4], P1[4], P2[4], P3[4];     // shifts 0..3 of 4 input rows
                #pragma unroll
                for (int r = 0; r < 4; r++) {
                    uint32_t wa = s.qin[base + r * 7];
                    uint32_t wb = s.qin[base + r * 7 + 1];
                    P0[r] = wa;
                    P1[r] = __byte_perm(wa, wb, 0x4321);
                    P2[r] = __byte_perm(wa, wb, 0x5432);
                    P3[r] = __byte_perm(wa, wb, 0x6543);
                }
                uint32_t ow0 = 0, ow1 = 0;
                #pragma unroll
                for (int oc = 0; oc < 4; oc++) {
                    int k0 = wp1[oc][0], k1 = wp1[oc][1], k2 = wp1[oc][2];
                    // pooled output px0: conv pixels at shifts 0,1 x row offsets 0,1
                    int a00 = dp3(P0[0], P0[1], P0[2], k0, k1, k2);
                    int a01 = dp3(P1[0], P1[1], P1[2], k0, k1, k2);
                    int a10 = dp3(P0[1], P0[2], P0[3], k0, k1, k2);
                    int a11 = dp3(P1[1], P1[2], P1[3], k0, k1, k2);
                    int m0 = max(max(max(a00, a01), max(a10, a11)), 0);
                    ow0 |= (uint32_t)qnc(m0, C1F, I1F) << (8 * oc);
                    // pooled output px0+1: shifts 2,3
                    int b00 = dp3(P2[0], P2[1], P2[2], k0, k1, k2);
                    int b01 = dp3(P3[0], P3[1], P3[2], k0, k1, k2);
                    int b10 = dp3(P2[1], P2[2], P2[3], k0, k1, k2);
                    int b11 = dp3(P3[1], P3[2], P3[3], k0, k1, k2);
                    int m1 = max(max(max(b00, b01), max(b10, b11)), 0);
                    ow1 |= (uint32_t)qnc(m1, C1F, I1F) << (8 * oc);
                }
                s.q2[base + pp] = ow0;                   // py*14 + 2*pp
                if (pp < 6) s.q2[base + pp + 1] = ow1;   // px=13 pair half discarded
            }
        }
    }
    __syncwarp();

    // ---- stage 2: conv2(3x3,4->4) + maxpool2x2 + relu + quant -> q3[25] ----
    if (lane < 25) {
        int py = lane / 5, px = lane - py * 5;
        const uint2* qb = (const uint2*)(s.q2 + (2 * py) * 14 + 2 * px);
        uint32_t rw[4][4];
        #pragma unroll
        for (int r = 0; r < 4; r++) {
            uint2 a = qb[r * 7], b = qb[r * 7 + 1];
            rw[r][0] = a.x; rw[r][1] = a.y; rw[r][2] = b.x; rw[r][3] = b.y;
        }
        int q[4];
        #pragma unroll
        for (int oc = 0; oc < 4; oc++) {
            const int* wo = wp2[oc];
            int m = 0; bool first = true;
            #pragma unroll
            for (int dy = 0; dy < 2; dy++)
                #pragma unroll
                for (int dx = 0; dx < 2; dx++) {
                    int a = 0;
                    #pragma unroll
                    for (int ky = 0; ky < 3; ky++)
                        #pragma unroll
                        for (int kx = 0; kx < 3; kx++)
                            a = __dp4a((int)rw[dy + ky][dx + kx], wo[ky * 3 + kx], a);
                    m = first ? a : max(m, a); first = false;
                }
            m = max(m, 0);
            q[oc] = qcl(m, C2F, I2F);
        }
        s.q3[lane] = pack4(q[0], q[1], q[2], q[3]);
    }
    __syncwarp();

    // ---- stage 3: conv3(3x3,4->4) -> 3x3, pool3x3 + relu + quant (shuffle reduce) ----
    int acc0 = 0, acc1 = 0, acc2 = 0, acc3 = 0;   // zeros = relu floor on idle lanes
    if (lane < 9) {
        int py = lane / 3, px = lane - py * 3;
        uint32_t v[9];
        #pragma unroll
        for (int ky = 0; ky < 3; ky++)
            #pragma unroll
            for (int kx = 0; kx < 3; kx++)
                v[ky * 3 + kx] = s.q3[(py + ky) * 5 + px + kx];
        #pragma unroll
        for (int k = 0; k < 9; k++) {
            acc0 = __dp4a((int)v[k], wp3[0][k], acc0);
            acc1 = __dp4a((int)v[k], wp3[1][k], acc1);
            acc2 = __dp4a((int)v[k], wp3[2][k], acc2);
            acc3 = __dp4a((int)v[k], wp3[3][k], acc3);
        }
    }
    #pragma unroll
    for (int off = 8; off > 0; off >>= 1) {
        acc0 = max(acc0, __shfl_xor_sync(0xFFFFFFFFu, acc0, off));
        acc1 = max(acc1, __shfl_xor_sync(0xFFFFFFFFu, acc1, off));
        acc2 = max(acc2, __shfl_xor_sync(0xFFFFFFFFu, acc2, off));
        acc3 = max(acc3, __shfl_xor_sync(0xFFFFFFFFu, acc3, off));
    }
    int q4w = (int)pack4(qcl(acc0, C3F, I3F), qcl(acc1, C3F, I3F),
                         qcl(acc2, C3F, I3F), qcl(acc3, C3F, I3F));

    // ---- stage 4: conv4(1x1,4->12) + relu; emit channels 0..9 ----
    if (lane < 10) {
        int a = __dp4a(q4w, wp4[lane], 0);
        out[(size_t)img * 10 + lane] = fmaxf(__fmul_rn(__int2float_rn(a), C4F), 0.0f);
    }
}

} // namespace

extern "C" void kernel_launch(void* const* d_in, const int* in_sizes, int n_in,
                              void* d_out, int out_size) {
    const float* x  = (const float*)d_in[0];
    const float* w1 = (const float*)d_in[1];
    const float* w2 = (const float*)d_in[2];
    const float* w3 = (const float*)d_in[3];
    const float* w4 = (const float*)d_in[4];
    float* out = (float*)d_out;

    int B = in_sizes[0] / 784;
    int blocks = (B + WPB - 1) / WPB;
    qcnn_kernel<<<blocks, THREADS>>>(x, w1, w2, w3, w4, out, B);
}

// round 15
// speedup vs baseline: 1.0446x; 1.0446x over previous
#include <cuda_runtime.h>
#include <stdint.h>

namespace {

constexpr int WPB = 4;                  // warps (= images) per block
constexpr int THREADS = WPB * 32;

// Scale chain in double exactly like Python floats, cast to f32 at use.
constexpr double S0d = 0.05;
constexpr double C1d = S0d * 0.05;
constexpr double S1d = C1d * 16.0;
constexpr double C2d = S1d * 0.05;
constexpr double S2d = C2d * 16.0;
constexpr double C3d = S2d * 0.05;
constexpr double S3d = C3d * 16.0;
constexpr double C4d = S3d * 0.05;

// XLA rewrites x/const -> x * fl32(1/const)
constexpr float I0F = 1.0f / (float)S0d;
constexpr float C1F = (float)C1d;  constexpr float I1F = 1.0f / (float)S1d;
constexpr float C2F = (float)C2d;  constexpr float I2F = 1.0f / (float)S2d;
constexpr float C3F = (float)C3d;  constexpr float I3F = 1.0f / (float)S3d;
constexpr float C4F = (float)C4d;

constexpr float RMAG = 8388608.0f;       // 2^23  (nonneg round magic)
constexpr float SMAG = 12582912.0f;      // 2^23+2^22 (signed i2f magic)

__device__ __forceinline__ int f2i(float f) { return __float2int_rn(f); }

__device__ __forceinline__ int pk(int a, int b, int c, int d) {
    return (a & 255) | ((b & 255) << 8) | ((c & 255) << 16) | ((d & 255) << 24);
}

// exact i2f for 0 <= m < 2^23, on alu/fma pipes (no I2F)
__device__ __forceinline__ float i2f_nn(int m) {
    return __int_as_float(0x4B000000 + m) - RMAG;
}

// Quantize, no clamp (stage 1; 0 <= m <= 1440 -> q <= 90 < 128).
// Result float bits = 0x4B000000 | q : byte0 IS the quantized value.
// fl(z + 2^23) = 2^23 + RNE(z) (ties-to-even) == __float2int_rn(z) exactly.
__device__ __forceinline__ int qncf(int m, float C, float I) {
    float z = __fmul_rn(__fmul_rn(i2f_nn(m), C), I);
    return __float_as_int(z + RMAG);
}
// Clamped quantize (m >= 0 post-relu, only upper clip can bind; q <= 127).
__device__ __forceinline__ int qclf(int m, float C, float I) {
    float z = fminf(__fmul_rn(__fmul_rn(i2f_nn(m), C), I), 127.0f);
    return __float_as_int(z + RMAG);
}

// (a.b0, b.b0, c.b0, d.b0) -> one word. Selector nibbles LSB-first.
__device__ __forceinline__ uint32_t pack4(int a, int b, int c, int d) {
    return __byte_perm(__byte_perm(a, b, 0x0040), __byte_perm(c, d, 0x0040), 0x5410);
}

__device__ __forceinline__ int dp3(uint32_t r0, uint32_t r1, uint32_t r2,
                                   int k0, int k1, int k2) {
    return __dp4a((int)r0, k0, __dp4a((int)r1, k1, __dp4a((int)r2, k2, 0)));
}

struct __align__(16) WS {
    uint32_t qin[198];       // 28 rows x 7 words, contiguous (+2 pad: OOB guard + align)
    uint32_t q2[13 * 14];    // 13 rows, stride 14 words (even => 8B-aligned uint2 reads)
    uint32_t q3[26];         // 5x5 cells, 4 ch packed per word (+pad)
};

__global__ void __launch_bounds__(THREADS, 12) qcnn_kernel(
    const float* __restrict__ x,
    const float* __restrict__ w1,
    const float* __restrict__ w2,
    const float* __restrict__ w3,
    const float* __restrict__ w4,
    float* __restrict__ out,
    int B)
{
    __shared__ WS ws[WPB];
    __shared__ int wp1[4][3];   // [oc][ky]: (w[ky,0],w[ky,1],w[ky,2],0)
    __shared__ int wp2[4][9];   // [oc][ky*3+kx]: 4 in-ch packed
    __shared__ int wp3[4][9];
    __shared__ int wp4[12];

    const int tid = threadIdx.x;

    // ---- pack integer weights into dp4a operands (once per block) ----
    if (tid < 12) {
        int oc = tid / 3, ky = tid % 3;
        const float* p = w1 + (ky * 3) * 16 + oc;     // HWIO, ic=0, kx stride 16
        wp1[oc][ky] = pk(f2i(p[0]), f2i(p[16]), f2i(p[32]), 0);
    } else if (tid < 48) {
        int j = tid - 12, oc = j / 9, k = j % 9;
        const float* p = w2 + k * 16 + oc;
        wp2[oc][k] = pk(f2i(p[0]), f2i(p[4]), f2i(p[8]), f2i(p[12]));
    } else if (tid < 84) {
        int j = tid - 48, oc = j / 9, k = j % 9;
        const float* p = w3 + k * 16 + oc;
        wp3[oc][k] = pk(f2i(p[0]), f2i(p[4]), f2i(p[8]), f2i(p[12]));
    } else if (tid < 96) {
        int oc = tid - 84;
        wp4[oc] = pk(f2i(w4[oc]), f2i(w4[12 + oc]), f2i(w4[24 + oc]), f2i(w4[36 + oc]));
    }
    __syncthreads();

    const int lane = tid & 31;
    const int wrp  = tid >> 5;
    const int img  = blockIdx.x * WPB + wrp;
    if (img >= B) return;
    WS& s = ws[wrp];

    // ---- stage 0: quantize input via round-magic; pack 4 px/word ----
    // x in [0,1) => q in [0,20]; t + 2^23 has byte0 = RNE(t) exactly.
    {
        const float4* xi4 = (const float4*)(x + (size_t)img * 784);
        for (int g = lane; g < 196; g += 32) {
            float4 v = xi4[g];
            int a = __float_as_int(__fmul_rn(v.x, I0F) + RMAG);
            int b = __float_as_int(__fmul_rn(v.y, I0F) + RMAG);
            int c = __float_as_int(__fmul_rn(v.z, I0F) + RMAG);
            int d = __float_as_int(__fmul_rn(v.w, I0F) + RMAG);
            s.qin[g] = pack4(a, b, c, d);
        }
    }
    __syncwarp();

    // ---- stage 1: conv1(3x3,1->4) + maxpool2x2 + relu + quant -> q2[13][13] ----
    // Fused px-pair tasks: task u = (py, pp) computes pooled outputs px0=2pp, px0+1.
    {
        #pragma unroll
        for (int it = 0; it < 3; it++) {
            int u = lane + it * 32;
            if (u < 91) {
                int py = u / 7, pp = u - py * 7;
                int base = py * 14 + pp;                 // word of byte 4*pp in row 2*py
                uint32_t P0[4], P1[4], P2[4], P3[4];     // shifts 0..3 of 4 input rows
                #pragma unroll
                for (int r = 0; r < 4; r++) {
                    uint32_t wa = s.qin[base + r * 7];
                    uint32_t wb = s.qin[base + r * 7 + 1];
                    P0[r] = wa;
                    P1[r] = __byte_perm(wa, wb, 0x4321);
                    P2[r] = __byte_perm(wa, wb, 0x5432);
                    P3[r] = __byte_perm(wa, wb, 0x6543);
                }
                int q0[4], q1[4];
                #pragma unroll
                for (int oc = 0; oc < 4; oc++) {
                    int k0 = wp1[oc][0], k1 = wp1[oc][1], k2 = wp1[oc][2];
                    // pooled output px0: conv pixels at shifts 0,1 x row offsets 0,1
                    int a00 = dp3(P0[0], P0[1], P0[2], k0, k1, k2);
                    int a01 = dp3(P1[0], P1[1], P1[2], k0, k1, k2);
                    int a10 = dp3(P0[1], P0[2], P0[3], k0, k1, k2);
                    int a11 = dp3(P1[1], P1[2], P1[3], k0, k1, k2);
                    int m0 = max(max(max(a00, a01), max(a10, a11)), 0);
                    q0[oc] = qncf(m0, C1F, I1F);
                    // pooled output px0+1: shifts 2,3
                    int b00 = dp3(P2[0], P2[1], P2[2], k0, k1, k2);
                    int b01 = dp3(P3[0], P3[1], P3[2], k0, k1, k2);
                    int b10 = dp3(P2[1], P2[2], P2[3], k0, k1, k2);
                    int b11 = dp3(P3[1], P3[2], P3[3], k0, k1, k2);
                    int m1 = max(max(max(b00, b01), max(b10, b11)), 0);
                    q1[oc] = qncf(m1, C1F, I1F);
                }
                s.q2[base + pp] = pack4(q0[0], q0[1], q0[2], q0[3]);   // py*14 + 2*pp
                if (pp < 6)
                    s.q2[base + pp + 1] = pack4(q1[0], q1[1], q1[2], q1[3]);
            }
        }
    }
    __syncwarp();

    // ---- stage 2: conv2(3x3,4->4) + maxpool2x2 + relu + quant -> q3[25] ----
    if (lane < 25) {
        int py = lane / 5, px = lane - py * 5;
        const uint2* qb = (const uint2*)(s.q2 + (2 * py) * 14 + 2 * px);
        uint32_t rw[4][4];
        #pragma unroll
        for (int r = 0; r < 4; r++) {
            uint2 a = qb[r * 7], b = qb[r * 7 + 1];
            rw[r][0] = a.x; rw[r][1] = a.y; rw[r][2] = b.x; rw[r][3] = b.y;
        }
        int q[4];
        #pragma unroll
        for (int oc = 0; oc < 4; oc++) {
            const int* wo = wp2[oc];
            int m = 0; bool first = true;
            #pragma unroll
            for (int dy = 0; dy < 2; dy++)
                #pragma unroll
                for (int dx = 0; dx < 2; dx++) {
                    int a = 0;
                    #pragma unroll
                    for (int ky = 0; ky < 3; ky++)
                        #pragma unroll
                        for (int kx = 0; kx < 3; kx++)
                            a = __dp4a((int)rw[dy + ky][dx + kx], wo[ky * 3 + kx], a);
                    m = first ? a : max(m, a); first = false;
                }
            m = max(m, 0);
            q[oc] = qclf(m, C2F, I2F);
        }
        s.q3[lane] = pack4(q[0], q[1], q[2], q[3]);
    }
    __syncwarp();

    // ---- stage 3: conv3(3x3,4->4) -> 3x3, pool3x3 + relu + quant (shuffle reduce) ----
    int acc0 = 0, acc1 = 0, acc2 = 0, acc3 = 0;   // zeros = relu floor on idle lanes
    if (lane < 9) {
        int py = lane / 3, px = lane - py * 3;
        uint32_t v[9];
        #pragma unroll
        for (int ky = 0; ky < 3; ky++)
            #pragma unroll
            for (int kx = 0; kx < 3; kx++)
                v[ky * 3 + kx] = s.q3[(py + ky) * 5 + px + kx];
        #pragma unroll
        for (int k = 0; k < 9; k++) {
            acc0 = __dp4a((int)v[k], wp3[0][k], acc0);
            acc1 = __dp4a((int)v[k], wp3[1][k], acc1);
            acc2 = __dp4a((int)v[k], wp3[2][k], acc2);
            acc3 = __dp4a((int)v[k], wp3[3][k], acc3);
        }
    }
    #pragma unroll
    for (int off = 8; off > 0; off >>= 1) {
        acc0 = max(acc0, __shfl_xor_sync(0xFFFFFFFFu, acc0, off));
        acc1 = max(acc1, __shfl_xor_sync(0xFFFFFFFFu, acc1, off));
        acc2 = max(acc2, __shfl_xor_sync(0xFFFFFFFFu, acc2, off));
        acc3 = max(acc3, __shfl_xor_sync(0xFFFFFFFFu, acc3, off));
    }
    int q4w = (int)pack4(qclf(acc0, C3F, I3F), qclf(acc1, C3F, I3F),
                         qclf(acc2, C3F, I3F), qclf(acc3, C3F, I3F));

    // ---- stage 4: conv4(1x1,4->12) + relu; emit channels 0..9 ----
    if (lane < 10) {
        int a = __dp4a(q4w, wp4[lane], 0);
        float f = __int_as_float(0x4B400000 + a) - SMAG;   // exact i2f, |a| < 2^22
        out[(size_t)img * 10 + lane] = fmaxf(__fmul_rn(f, C4F), 0.0f);
    }
}

} // namespace

extern "C" void kernel_launch(void* const* d_in, const int* in_sizes, int n_in,
                              void* d_out, int out_size) {
    const float* x  = (const float*)d_in[0];
    const float* w1 = (const float*)d_in[1];
    const float* w2 = (const float*)d_in[2];
    const float* w3 = (const float*)d_in[3];
    const float* w4 = (const float*)d_in[4];
    float* out = (float*)d_out;

    int B = in_sizes[0] / 784;
    int blocks = (B + WPB - 1) / WPB;
    qcnn_kernel<<<blocks, THREADS>>>(x, w1, w2, w3, w4, out, B);
}